// round 16
// baseline (speedup 1.0000x reference)
#include <cuda_runtime.h>
#include <math.h>

#define DX 16
#define DY 16
#define TT 50
#define BB 64
#define NMC 100
#define MM 128
#define HID 64
#define PVAR (0.05f*0.05f)
#define EVAR (0.1f*0.1f)
#define JIT 1e-4f
#define LOG2PI 1.8378770664093453f
#define LOG2E 1.44269504088896f

__device__ float g_state[BB*NMC*DX];
__device__ float g_f[BB*NMC*DX];
__device__ float g_z2[DX*MM];
__device__ float g_aOs[DX*MM];
__device__ float g_karg[DX];
__device__ float g_taper[DX*DX];
__device__ double g_kl0, g_gpkl, g_ll;

__device__ __forceinline__ float sigf(float x){ return 1.f/(1.f+expf(-x)); }
__device__ __forceinline__ float splus(float x){ return x>20.f? x : log1pf(expf(x)); }
__device__ __forceinline__ float lrelu(float x){ return x>0.f? x : 0.01f*x; }

// ---------- K0 ----------
__global__ void k0_init(){
    int t=threadIdx.x;
    if(t==0){ g_kl0=0.0; g_gpkl=0.0; g_ll=0.0; }
    if(t<256){
        int i=t>>4, j=t&15;
        int df=i-j; if(df<0)df=-df;
        int dist = df<(16-df)?df:(16-df);
        double z=(double)dist/5.0, g;
        double z2=z*z,z3=z2*z,z4=z3*z,z5=z4*z;
        if(z<1.0)      g=1.0-(5.0/3.0)*z2+(5.0/8.0)*z3+0.5*z4-0.25*z5;
        else if(z<2.0) g=4.0-5.0*z+(5.0/3.0)*z2+(5.0/8.0)*z3-0.5*z4+(1.0/12.0)*z5-2.0/(3.0*z);
        else g=0.0;
        g_taper[t]=(float)g;
    }
}

// ---------- K1: LSTM ----------
__global__ void __launch_bounds__(256) k1_lstm(
    const float* __restrict__ obs, const float* __restrict__ eps,
    const float* __restrict__ Wih, const float* __restrict__ Whh,
    const float* __restrict__ bl, const float* __restrict__ Wm,
    const float* __restrict__ bm, const float* __restrict__ Wv,
    const float* __restrict__ bv)
{
    __shared__ float hs[64], cs[64], ys[16], gt[256], m0[16], sq0[16], klp[16];
    int tid=threadIdx.x, b=blockIdx.x;
    float wih[16];
#pragma unroll
    for(int k=0;k<16;++k) wih[k]=Wih[tid*16+k];
    float whh[64];
#pragma unroll
    for(int k=0;k<64;++k) whh[k]=Whh[tid*64+k];
    float bias=bl[tid];
    if(tid<64){ hs[tid]=0.f; cs[tid]=0.f; }
    __syncthreads();
    for(int t=0;t<TT;++t){
        if(tid<16) ys[tid]=obs[(b*TT+t)*16+tid];
        __syncthreads();
        float g=bias;
#pragma unroll
        for(int k=0;k<16;++k) g+=ys[k]*wih[k];
#pragma unroll
        for(int k=0;k<64;++k) g+=hs[k]*whh[k];
        gt[tid]=g;
        __syncthreads();
        if(tid<64){
            float iv=sigf(gt[tid]), fv=sigf(gt[64+tid]);
            float gv=tanhf(gt[128+tid]), ov=sigf(gt[192+tid]);
            float c=fv*cs[tid]+iv*gv;
            cs[tid]=c; hs[tid]=ov*tanhf(c);
        }
        __syncthreads();
    }
    if(tid<16){
        float m=bm[tid], vr=bv[tid];
#pragma unroll
        for(int j=0;j<64;++j){ float h=hs[j]; m+=h*Wm[tid*64+j]; vr+=h*Wv[tid*64+j]; }
        float v=splus(vr)+1e-4f;
        m0[tid]=m; sq0[tid]=sqrtf(v);
        klp[tid]=v+m*m-1.f-logf(v);
    }
    __syncthreads();
    if(tid==0){
        float s=0.f;
#pragma unroll
        for(int k=0;k<16;++k) s+=klp[k];
        atomicAdd(&g_kl0,(double)(0.5f*s)/64.0);
    }
    for(int idx=tid; idx<NMC*16; idx+=256){
        int n=idx>>4, k=idx&15;
        g_state[(b*NMC+n)*16+k]=m0[k]+sq0[k]*eps[(n*BB+b)*16+k];
    }
}

// ---------- K3: sparse-GP precompute ----------
__global__ void __launch_bounds__(128) k3_gp(
    const float* __restrict__ Z, const float* __restrict__ lls,
    const float* __restrict__ los, const float* __restrict__ qmu,
    const float* __restrict__ qL)
{
    extern __shared__ float sh[];
    float* Ku=sh;            // 128*128
    float* Zd=Ku+16384;      // 128*17
    float* z2=Zd+2176;       // 128
    float* bvv=z2+128;       // 128
    float* al=bvv+128;       // 128
    float* red=al+128;       // 128
    int tid=threadIdx.x, d=blockIdx.x;
    float ls2=expf(2.f*lls[d]);
    float karg=-0.5f/ls2;
    float osc=expf(los[d]);
    if(tid==0) g_karg[d]=karg;
    for(int i=tid;i<2048;i+=128) Zd[(i>>4)*17+(i&15)]=Z[d*2048+i];
    __syncthreads();
    { float s=0.f;
#pragma unroll
      for(int k=0;k<16;++k) s+=Zd[tid*17+k]*Zd[tid*17+k];
      z2[tid]=s; g_z2[d*128+tid]=s; }
    __syncthreads();
    for(int idx=tid;idx<16384;idx+=128){
        int i=idx>>7, j=idx&127;
        float dot=0.f;
#pragma unroll
        for(int k=0;k<16;++k) dot+=Zd[i*17+k]*Zd[j*17+k];
        float sq=z2[i]+z2[j]-2.f*dot;
        Ku[idx]=osc*expf(karg*sq)+(i==j?JIT:0.f);
    }
    __syncthreads();
    for(int k=0;k<128;++k){
        if(tid==0) Ku[k*128+k]=sqrtf(Ku[k*128+k]);
        __syncthreads();
        int i=k+1+tid;
        if(i<128) Ku[i*128+k]/=Ku[k*128+k];
        __syncthreads();
        if(i<128){
            float lik=Ku[i*128+k];
            for(int j=k+1;j<=i;++j) Ku[i*128+j]-=lik*Ku[j*128+k];
        }
        __syncthreads();
    }
    if(tid<32){
        int lane=tid;
        for(int i=0;i<128;++i){
            float s=0.f;
            for(int j=lane;j<i;j+=32) s+=Ku[i*128+j]*bvv[j];
#pragma unroll
            for(int off=16;off;off>>=1) s+=__shfl_down_sync(0xffffffffu,s,off);
            if(lane==0) bvv[i]=(qmu[d*128+i]-s)/Ku[i*128+i];
            __syncwarp();
        }
        for(int i=127;i>=0;--i){
            float s=0.f;
            for(int j=i+1+lane;j<128;j+=32) s+=Ku[j*128+i]*al[j];
#pragma unroll
            for(int off=16;off;off>>=1) s+=__shfl_down_sync(0xffffffffu,s,off);
            if(lane==0) al[i]=(bvv[i]-s)/Ku[i*128+i];
            __syncwarp();
        }
    }
    __syncthreads();
    g_aOs[d*128+tid]=al[tid]*osc;
    float a[128]; float sA2=0.f;
    for(int i=0;i<128;++i){
        float s=qL[(d*128+i)*128+tid];
        for(int j=0;j<i;++j) s-=Ku[i*128+j]*a[j];
        float v=s/Ku[i*128+i];
        a[i]=v; sA2+=v*v;
    }
    red[tid]=sA2;
    __syncthreads();
    if(tid==0){
        double tot=0.0;
        for(int t=0;t<128;++t) tot+=(double)red[t];
        double sb2=0.0, ldK=0.0, ldS=0.0;
        for(int i=0;i<128;++i){
            sb2+=(double)bvv[i]*(double)bvv[i];
            ldK+=(double)logf(Ku[i*128+i]);
            ldS+=(double)logf(fabsf(qL[(d*128+i)*128+i]));
        }
        atomicAdd(&g_gpkl,(0.5*(tot+sb2-128.0+2.0*ldK-2.0*ldS))/(50.0*64.0));
    }
}

// ---------- kGP: measured-best (grid 16x25, 1 pt/thread, exp2 prescale) ----------
__global__ void __launch_bounds__(256) kGP(const float* __restrict__ Z)
{
    __shared__ float Zs[2048];
    __shared__ float2 zA[128];
    int tid=threadIdx.x, d=blockIdx.x;
    float kargl=g_karg[d]*LOG2E;
    {
        float s2=-2.f*kargl;
        const float4* Zg=(const float4*)(Z+d*2048);
        float4* Zs4=(float4*)Zs;
        for(int i=tid;i<512;i+=256){
            float4 v=Zg[i];
            v.x*=s2; v.y*=s2; v.z*=s2; v.w*=s2;
            Zs4[i]=v;
        }
        if(tid<128) zA[tid]=make_float2(kargl*g_z2[d*128+tid], g_aOs[d*128+tid]);
    }
    __syncthreads();
    int p = blockIdx.y*256 + tid;
    const float4* xg=(const float4*)(g_state + p*16);
    float4 a0=xg[0],a1=xg[1],a2=xg[2],a3=xg[3];
    float x[16]={a0.x,a0.y,a0.z,a0.w,a1.x,a1.y,a1.z,a1.w,
                 a2.x,a2.y,a2.z,a2.w,a3.x,a3.y,a3.z,a3.w};
    float x2=0.f;
#pragma unroll
    for(int k=0;k<16;++k) x2+=x[k]*x[k];
    float kx2=kargl*x2;
    float acc=0.f;
#pragma unroll 8
    for(int m=0;m<128;++m){
        const float4* zr=(const float4*)(Zs+m*16);
        float4 z0=zr[0],z1=zr[1],z2v=zr[2],z3=zr[3];
        float2 za=zA[m];
        float arg=kx2+za.x;
        arg+=x[0]*z0.x+x[1]*z0.y+x[2]*z0.z+x[3]*z0.w
            +x[4]*z1.x+x[5]*z1.y+x[6]*z1.z+x[7]*z1.w
            +x[8]*z2v.x+x[9]*z2v.y+x[10]*z2v.z+x[11]*z2v.w
            +x[12]*z3.x+x[13]*z3.y+x[14]*z3.z+x[15]*z3.w;
        acc+=za.y*exp2f(arg);
    }
    g_f[p*16+d]=acc;
}

// ---------- kFlow: RealNVP, 16 pts/block, 400 blocks ----------
// No SMEM weight staging: weights read from L1/L2 (uniform per warp, L2-resident).
// s and t nets computed in parallel phases. 17 syncs/block, ~15 KB SMEM.
struct FLsm {
    float cur[16*17];
    float h1[2][16*33];
    float h2[2][16*65];
    float st[2][16*9];
};

__global__ void __launch_bounds__(256) kFlow(
    const float* __restrict__ sW1, const float* __restrict__ sb1,
    const float* __restrict__ sW2, const float* __restrict__ sb2,
    const float* __restrict__ sW3, const float* __restrict__ sb3,
    const float* __restrict__ tW1, const float* __restrict__ tb1,
    const float* __restrict__ tW2, const float* __restrict__ tb2,
    const float* __restrict__ tW3, const float* __restrict__ tb3)
{
    __shared__ FLsm sm;
    int tid=threadIdx.x, q0=blockIdx.x*16;
    sm.cur[(tid>>4)*17+(tid&15)]=g_f[q0*16+tid];
    __syncthreads();
    for(int l=0;l<4;++l){
        bool odd=(l&1)!=0;
        int act   = odd?0:8;
        int inact = odd?8:0;
        // L1: 2 nets x 32 j x 16 p = 1024 items
        for(int idx=tid;idx<1024;idx+=256){
            int net=idx>>9, r=idx&511, j=r>>4, p=r&15;
            const float* W1=(net? tW1 : sW1)+l*512+j*16+act;
            const float* b1=(net? tb1 : sb1)+l*32;
            const float4* w4=(const float4*)W1;
            float4 w0=w4[0], w1=w4[1];
            const float* xr=sm.cur+p*17+act;
            float a=__ldg(b1+j)
                +xr[0]*w0.x+xr[1]*w0.y+xr[2]*w0.z+xr[3]*w0.w
                +xr[4]*w1.x+xr[5]*w1.y+xr[6]*w1.z+xr[7]*w1.w;
            sm.h1[net][p*33+j]=lrelu(a);
        }
        __syncthreads();
        // L2: 2 nets x 64 j x 16 p = 2048 items
        for(int idx=tid;idx<2048;idx+=256){
            int net=idx>>10, r=idx&1023, j=r>>4, p=r&15;
            const float4* w4=(const float4*)((net? tW2 : sW2)+l*2048+j*32);
            const float* b2=(net? tb2 : sb2)+l*64;
            const float* hr=sm.h1[net]+p*33;
            float a=__ldg(b2+j);
#pragma unroll
            for(int q=0;q<8;++q){
                float4 w=w4[q];
                a+=hr[4*q]*w.x+hr[4*q+1]*w.y+hr[4*q+2]*w.z+hr[4*q+3]*w.w;
            }
            sm.h2[net][p*65+j]=lrelu(a);
        }
        __syncthreads();
        // L3: 2 nets x 8 j x 16 p = 256 items (only inactive outputs)
        {
            int net=tid>>7, r=tid&127, j=r>>4, p=r&15, jd=inact+j;
            const float4* w4=(const float4*)((net? tW3 : sW3)+l*1024+jd*64);
            const float* b3=(net? tb3 : sb3)+l*16;
            const float* hr=sm.h2[net]+p*65;
            float a=__ldg(b3+jd);
#pragma unroll
            for(int q=0;q<16;++q){
                float4 w=w4[q];
                a+=hr[4*q]*w.x+hr[4*q+1]*w.y+hr[4*q+2]*w.z+hr[4*q+3]*w.w;
            }
            sm.st[net][p*9+j]=a;
        }
        __syncthreads();
        // update: 8 j x 16 p = 128 items
        if(tid<128){
            int p=tid&15, j=tid>>4, jd=inact+j;
            float xv=sm.cur[p*17+jd];
            sm.cur[p*17+jd]=xv*expf(sm.st[0][p*9+j])+sm.st[1][p*9+j];
        }
        __syncthreads();
    }
    g_state[q0*16+tid]=sm.cur[(tid>>4)*17+(tid&15)];
}

// ---------- kB: EnKF, 512 threads (R11 proven) ----------
__global__ void __launch_bounds__(512) kB_enkf(
    const float* __restrict__ obs, const float* __restrict__ Hg,
    float* __restrict__ out, int t)
{
    __shared__ float Xs[NMC*17], inn[NMC*17];
    __shared__ float Hs[256], Pm[256], Ss[256], Kt[256], PHt[256], KH[256];
    __shared__ float Xm[16], ys[16], dd[16], sol16[16];
    __shared__ float cov2[512], xm4[64];
    int tid=threadIdx.x, b=blockIdx.x;
    for(int i=tid;i<NMC*16;i+=512) Xs[(i>>4)*17+(i&15)]=g_state[b*NMC*16+i];
    if(tid<256) Hs[tid]=Hg[tid];
    if(tid<16) ys[tid]=obs[(b*TT+t)*16+tid];
    __syncthreads();
    if(tid<64){
        int d=tid&15, q=tid>>4;
        float s=0.f;
        for(int n=q*25;n<q*25+25;++n) s+=Xs[n*17+d];
        xm4[tid]=s;
    }
    __syncthreads();
    if(tid<16) Xm[tid]=(xm4[tid]+xm4[16+tid]+xm4[32+tid]+xm4[48+tid])/NMC;
    __syncthreads();
    {
        int pair=tid&255, half=tid>>8;
        int d=pair>>4, e=pair&15;
        float md=Xm[d], me=Xm[e], s=0.f;
        int n0=half*50;
        for(int n=n0;n<n0+50;++n) s+=(Xs[n*17+d]-md)*(Xs[n*17+e]-me);
        cov2[tid]=s;
    }
    __syncthreads();
    if(tid<256){
        int d=tid>>4, e=tid&15;
        Pm[tid]=g_taper[tid]*((cov2[tid]+cov2[tid+256])/(NMC-1))+(d==e?PVAR:0.f);
    }
    __syncthreads();
    if(tid<256){
        int o=tid>>4, d=tid&15;
        float s=0.f;
#pragma unroll
        for(int e=0;e<16;++e) s+=Hs[o*16+e]*Pm[e*16+d];
        PHt[tid]=s;
    }
    __syncthreads();
    if(tid<256){
        int o=tid>>4, pq=tid&15;
        float s=0.f;
#pragma unroll
        for(int d=0;d<16;++d) s+=PHt[o*16+d]*Hs[pq*16+d];
        Ss[tid]=s+(o==pq?EVAR:0.f);
    }
    if(tid>=256&&tid<272){
        int o=tid-256;
        float s=ys[o];
#pragma unroll
        for(int d=0;d<16;++d) s-=Xm[d]*Hs[o*16+d];
        dd[o]=s;
    }
    __syncthreads();
    if(tid<32){
#pragma unroll
        for(int k=0;k<16;++k){
            if(tid==0) Ss[k*16+k]=sqrtf(Ss[k*16+k]);
            __syncwarp();
            if(tid>k&&tid<16) Ss[tid*16+k]/=Ss[k*16+k];
            __syncwarp();
            if(tid>k&&tid<16){
                float lik=Ss[tid*16+k];
                for(int j=k+1;j<=tid;++j) Ss[tid*16+j]-=lik*Ss[j*16+k];
            }
            __syncwarp();
        }
    }
    __syncthreads();
    if(tid<17){
        float w[16], r[16];
#pragma unroll
        for(int i=0;i<16;++i) r[i]= (tid<16)? PHt[i*16+tid] : dd[i];
#pragma unroll
        for(int i=0;i<16;++i){
            float s=r[i];
#pragma unroll
            for(int j=0;j<16;++j) if(j<i) s-=Ss[i*16+j]*w[j];
            w[i]=s/Ss[i*16+i];
        }
#pragma unroll
        for(int i=15;i>=0;--i){
            float s=w[i];
#pragma unroll
            for(int j=15;j>=0;--j) if(j>i) s-=Ss[j*16+i]*w[j];
            w[i]=s/Ss[i*16+i];
        }
        if(tid<16){
#pragma unroll
            for(int i=0;i<16;++i) Kt[i*16+tid]=w[i];
        } else {
#pragma unroll
            for(int i=0;i<16;++i) sol16[i]=w[i];
        }
    }
    __syncthreads();
    for(int idx=tid;idx<NMC*16;idx+=512){
        int n=idx>>4, o=idx&15;
        float s=ys[o];
#pragma unroll
        for(int d=0;d<16;++d) s-=Xs[n*17+d]*Hs[o*16+d];
        inn[n*17+o]=s;
    }
    __syncthreads();
    for(int idx=tid;idx<NMC*16;idx+=512){
        int n=idx>>4, d=idx&15;
        float s=Xs[n*17+d];
#pragma unroll
        for(int o=0;o<16;++o) s+=inn[n*17+o]*Kt[o*16+d];
        Xs[n*17+d]=s;
        g_state[b*NMC*16+idx]=s;
    }
    if(tid<256){
        int d=tid>>4, e=tid&15;
        float s=0.f;
#pragma unroll
        for(int o=0;o<16;++o) s+=Kt[o*16+d]*Hs[o*16+e];
        KH[tid]=s;
    }
    __syncthreads();
    if(tid<64){
        int d=tid&15, q=tid>>4;
        float s=0.f;
        for(int n=q*25;n<q*25+25;++n) s+=Xs[n*17+d];
        xm4[tid]=s;
    }
    __syncthreads();
    if(tid<16){
        out[1+(b*TT+t)*16+tid]=(xm4[tid]+xm4[16+tid]+xm4[32+tid]+xm4[48+tid])/NMC;
        float pv=Pm[tid*16+tid];
#pragma unroll
        for(int e=0;e<16;++e) pv-=KH[tid*16+e]*Pm[e*16+tid];
        out[1+BB*TT*16+(b*TT+t)*16+tid]=pv;
    }
    if(tid==32){
        float quad=0.f, ld=0.f;
#pragma unroll
        for(int o=0;o<16;++o){ quad+=dd[o]*sol16[o]; ld+=logf(Ss[o*16+o]); }
        atomicAdd(&g_ll,(double)(-0.5f*(quad+2.f*ld+16.f*LOG2PI)));
    }
}

__global__ void kF_final(float* out){
    out[0]=(float)(-g_kl0-g_gpkl+g_ll/50.0);
}

extern "C" void kernel_launch(void* const* d_in, const int* in_sizes, int n_in,
                              void* d_out, int out_size)
{
    const float* obs =(const float*)d_in[0];
    const float* eps =(const float*)d_in[1];
    const float* Wih =(const float*)d_in[2];
    const float* Whh =(const float*)d_in[3];
    const float* bl  =(const float*)d_in[4];
    const float* Wm  =(const float*)d_in[5];
    const float* bm  =(const float*)d_in[6];
    const float* Wv  =(const float*)d_in[7];
    const float* bv  =(const float*)d_in[8];
    const float* Z   =(const float*)d_in[9];
    const float* lls =(const float*)d_in[10];
    const float* los =(const float*)d_in[11];
    const float* qmu =(const float*)d_in[12];
    const float* qL  =(const float*)d_in[13];
    const float* sW1 =(const float*)d_in[14];
    const float* sb1 =(const float*)d_in[15];
    const float* sW2 =(const float*)d_in[16];
    const float* sb2 =(const float*)d_in[17];
    const float* sW3 =(const float*)d_in[18];
    const float* sb3 =(const float*)d_in[19];
    const float* tW1 =(const float*)d_in[20];
    const float* tb1 =(const float*)d_in[21];
    const float* tW2 =(const float*)d_in[22];
    const float* tb2 =(const float*)d_in[23];
    const float* tW3 =(const float*)d_in[24];
    const float* tb3 =(const float*)d_in[25];
    const float* Hg  =(const float*)d_in[26];
    float* out=(float*)d_out;

    static int attr_done=0;
    if(!attr_done){
        cudaFuncSetAttribute(k3_gp, cudaFuncAttributeMaxDynamicSharedMemorySize, 80*1024);
        attr_done=1;
    }
    k0_init<<<1,256>>>();
    k1_lstm<<<64,256>>>(obs,eps,Wih,Whh,bl,Wm,bm,Wv,bv);
    k3_gp<<<16,128,80*1024>>>(Z,lls,los,qmu,qL);
    dim3 gGP(16,25);
    for(int t=0;t<TT;++t){
        kGP<<<gGP,256>>>(Z);
        kFlow<<<400,256>>>(sW1,sb1,sW2,sb2,sW3,sb3,tW1,tb1,tW2,tb2,tW3,tb3);
        kB_enkf<<<64,512>>>(obs,Hg,out,t);
    }
    kF_final<<<1,1>>>(out);
}

// round 17
// speedup vs baseline: 1.3097x; 1.3097x over previous
#include <cuda_runtime.h>
#include <math.h>

#define DX 16
#define DY 16
#define TT 50
#define BB 64
#define NMC 100
#define MM 128
#define HID 64
#define PVAR (0.05f*0.05f)
#define EVAR (0.1f*0.1f)
#define JIT 1e-4f
#define LOG2PI 1.8378770664093453f
#define LOG2E 1.44269504088896f

__device__ float g_state[BB*NMC*DX];
__device__ float g_f[BB*NMC*DX];
__device__ float g_z2[DX*MM];
__device__ float g_aOs[DX*MM];
__device__ float g_karg[DX];
__device__ float g_taper[DX*DX];
__device__ double g_kl0, g_gpkl, g_ll;

__device__ __forceinline__ float sigf(float x){ return 1.f/(1.f+expf(-x)); }
__device__ __forceinline__ float splus(float x){ return x>20.f? x : log1pf(expf(x)); }
__device__ __forceinline__ float lrelu(float x){ return x>0.f? x : 0.01f*x; }

// ---------- K0 ----------
__global__ void k0_init(){
    int t=threadIdx.x;
    if(t==0){ g_kl0=0.0; g_gpkl=0.0; g_ll=0.0; }
    if(t<256){
        int i=t>>4, j=t&15;
        int df=i-j; if(df<0)df=-df;
        int dist = df<(16-df)?df:(16-df);
        double z=(double)dist/5.0, g;
        double z2=z*z,z3=z2*z,z4=z3*z,z5=z4*z;
        if(z<1.0)      g=1.0-(5.0/3.0)*z2+(5.0/8.0)*z3+0.5*z4-0.25*z5;
        else if(z<2.0) g=4.0-5.0*z+(5.0/3.0)*z2+(5.0/8.0)*z3-0.5*z4+(1.0/12.0)*z5-2.0/(3.0*z);
        else g=0.0;
        g_taper[t]=(float)g;
    }
}

// ---------- K1: LSTM ----------
__global__ void __launch_bounds__(256) k1_lstm(
    const float* __restrict__ obs, const float* __restrict__ eps,
    const float* __restrict__ Wih, const float* __restrict__ Whh,
    const float* __restrict__ bl, const float* __restrict__ Wm,
    const float* __restrict__ bm, const float* __restrict__ Wv,
    const float* __restrict__ bv)
{
    __shared__ float hs[64], cs[64], ys[16], gt[256], m0[16], sq0[16], klp[16];
    int tid=threadIdx.x, b=blockIdx.x;
    float wih[16];
#pragma unroll
    for(int k=0;k<16;++k) wih[k]=Wih[tid*16+k];
    float whh[64];
#pragma unroll
    for(int k=0;k<64;++k) whh[k]=Whh[tid*64+k];
    float bias=bl[tid];
    if(tid<64){ hs[tid]=0.f; cs[tid]=0.f; }
    __syncthreads();
    for(int t=0;t<TT;++t){
        if(tid<16) ys[tid]=obs[(b*TT+t)*16+tid];
        __syncthreads();
        float g=bias;
#pragma unroll
        for(int k=0;k<16;++k) g+=ys[k]*wih[k];
#pragma unroll
        for(int k=0;k<64;++k) g+=hs[k]*whh[k];
        gt[tid]=g;
        __syncthreads();
        if(tid<64){
            float iv=sigf(gt[tid]), fv=sigf(gt[64+tid]);
            float gv=tanhf(gt[128+tid]), ov=sigf(gt[192+tid]);
            float c=fv*cs[tid]+iv*gv;
            cs[tid]=c; hs[tid]=ov*tanhf(c);
        }
        __syncthreads();
    }
    if(tid<16){
        float m=bm[tid], vr=bv[tid];
#pragma unroll
        for(int j=0;j<64;++j){ float h=hs[j]; m+=h*Wm[tid*64+j]; vr+=h*Wv[tid*64+j]; }
        float v=splus(vr)+1e-4f;
        m0[tid]=m; sq0[tid]=sqrtf(v);
        klp[tid]=v+m*m-1.f-logf(v);
    }
    __syncthreads();
    if(tid==0){
        float s=0.f;
#pragma unroll
        for(int k=0;k<16;++k) s+=klp[k];
        atomicAdd(&g_kl0,(double)(0.5f*s)/64.0);
    }
    for(int idx=tid; idx<NMC*16; idx+=256){
        int n=idx>>4, k=idx&15;
        g_state[(b*NMC+n)*16+k]=m0[k]+sq0[k]*eps[(n*BB+b)*16+k];
    }
}

// ---------- K3: sparse-GP precompute ----------
__global__ void __launch_bounds__(128) k3_gp(
    const float* __restrict__ Z, const float* __restrict__ lls,
    const float* __restrict__ los, const float* __restrict__ qmu,
    const float* __restrict__ qL)
{
    extern __shared__ float sh[];
    float* Ku=sh;            // 128*128
    float* Zd=Ku+16384;      // 128*17
    float* z2=Zd+2176;       // 128
    float* bvv=z2+128;       // 128
    float* al=bvv+128;       // 128
    float* red=al+128;       // 128
    int tid=threadIdx.x, d=blockIdx.x;
    float ls2=expf(2.f*lls[d]);
    float karg=-0.5f/ls2;
    float osc=expf(los[d]);
    if(tid==0) g_karg[d]=karg;
    for(int i=tid;i<2048;i+=128) Zd[(i>>4)*17+(i&15)]=Z[d*2048+i];
    __syncthreads();
    { float s=0.f;
#pragma unroll
      for(int k=0;k<16;++k) s+=Zd[tid*17+k]*Zd[tid*17+k];
      z2[tid]=s; g_z2[d*128+tid]=s; }
    __syncthreads();
    for(int idx=tid;idx<16384;idx+=128){
        int i=idx>>7, j=idx&127;
        float dot=0.f;
#pragma unroll
        for(int k=0;k<16;++k) dot+=Zd[i*17+k]*Zd[j*17+k];
        float sq=z2[i]+z2[j]-2.f*dot;
        Ku[idx]=osc*expf(karg*sq)+(i==j?JIT:0.f);
    }
    __syncthreads();
    for(int k=0;k<128;++k){
        if(tid==0) Ku[k*128+k]=sqrtf(Ku[k*128+k]);
        __syncthreads();
        int i=k+1+tid;
        if(i<128) Ku[i*128+k]/=Ku[k*128+k];
        __syncthreads();
        if(i<128){
            float lik=Ku[i*128+k];
            for(int j=k+1;j<=i;++j) Ku[i*128+j]-=lik*Ku[j*128+k];
        }
        __syncthreads();
    }
    if(tid<32){
        int lane=tid;
        for(int i=0;i<128;++i){
            float s=0.f;
            for(int j=lane;j<i;j+=32) s+=Ku[i*128+j]*bvv[j];
#pragma unroll
            for(int off=16;off;off>>=1) s+=__shfl_down_sync(0xffffffffu,s,off);
            if(lane==0) bvv[i]=(qmu[d*128+i]-s)/Ku[i*128+i];
            __syncwarp();
        }
        for(int i=127;i>=0;--i){
            float s=0.f;
            for(int j=i+1+lane;j<128;j+=32) s+=Ku[j*128+i]*al[j];
#pragma unroll
            for(int off=16;off;off>>=1) s+=__shfl_down_sync(0xffffffffu,s,off);
            if(lane==0) al[i]=(bvv[i]-s)/Ku[i*128+i];
            __syncwarp();
        }
    }
    __syncthreads();
    g_aOs[d*128+tid]=al[tid]*osc;
    float a[128]; float sA2=0.f;
    for(int i=0;i<128;++i){
        float s=qL[(d*128+i)*128+tid];
        for(int j=0;j<i;++j) s-=Ku[i*128+j]*a[j];
        float v=s/Ku[i*128+i];
        a[i]=v; sA2+=v*v;
    }
    red[tid]=sA2;
    __syncthreads();
    if(tid==0){
        double tot=0.0;
        for(int t=0;t<128;++t) tot+=(double)red[t];
        double sb2=0.0, ldK=0.0, ldS=0.0;
        for(int i=0;i<128;++i){
            sb2+=(double)bvv[i]*(double)bvv[i];
            ldK+=(double)logf(Ku[i*128+i]);
            ldS+=(double)logf(fabsf(qL[(d*128+i)*128+i]));
        }
        atomicAdd(&g_gpkl,(0.5*(tot+sb2-128.0+2.0*ldK-2.0*ldS))/(50.0*64.0));
    }
}

// ---------- kGP: R4 measured-best (2 pts/thread, 128 thr, grid 16x25) + exp2 ----------
__global__ void __launch_bounds__(128) kGP(const float* __restrict__ Z)
{
    __shared__ float Zs[2048];
    __shared__ float2 zA[128];
    int tid=threadIdx.x, d=blockIdx.x;
    float kargl=g_karg[d]*LOG2E;
    {
        float s2=-2.f*kargl;
        const float4* Zg=(const float4*)(Z+d*2048);
        float4* Zs4=(float4*)Zs;
        for(int i=tid;i<512;i+=128){
            float4 v=Zg[i];
            v.x*=s2; v.y*=s2; v.z*=s2; v.w*=s2;
            Zs4[i]=v;
        }
        zA[tid]=make_float2(kargl*g_z2[d*128+tid], g_aOs[d*128+tid]);
    }
    __syncthreads();
    int p0 = blockIdx.y*256 + tid*2;
    const float4* xg=(const float4*)(g_state + p0*16);
    float xa[16], xb[16];
    {
        float4 v;
#pragma unroll
        for(int q=0;q<4;++q){ v=xg[q];   xa[4*q]=v.x; xa[4*q+1]=v.y; xa[4*q+2]=v.z; xa[4*q+3]=v.w; }
#pragma unroll
        for(int q=0;q<4;++q){ v=xg[4+q]; xb[4*q]=v.x; xb[4*q+1]=v.y; xb[4*q+2]=v.z; xb[4*q+3]=v.w; }
    }
    float x2a=0.f, x2b=0.f;
#pragma unroll
    for(int k=0;k<16;++k){ x2a+=xa[k]*xa[k]; x2b+=xb[k]*xb[k]; }
    float kxa=kargl*x2a, kxb=kargl*x2b;
    float acca=0.f, accb=0.f;
#pragma unroll 4
    for(int m=0;m<128;++m){
        const float4* zr=(const float4*)(Zs+m*16);
        float4 z0=zr[0],z1=zr[1],z2v=zr[2],z3=zr[3];
        float2 za=zA[m];
        float ara=kxa+za.x, arb=kxb+za.x;
        ara+=xa[0]*z0.x+xa[1]*z0.y+xa[2]*z0.z+xa[3]*z0.w
            +xa[4]*z1.x+xa[5]*z1.y+xa[6]*z1.z+xa[7]*z1.w
            +xa[8]*z2v.x+xa[9]*z2v.y+xa[10]*z2v.z+xa[11]*z2v.w
            +xa[12]*z3.x+xa[13]*z3.y+xa[14]*z3.z+xa[15]*z3.w;
        arb+=xb[0]*z0.x+xb[1]*z0.y+xb[2]*z0.z+xb[3]*z0.w
            +xb[4]*z1.x+xb[5]*z1.y+xb[6]*z1.z+xb[7]*z1.w
            +xb[8]*z2v.x+xb[9]*z2v.y+xb[10]*z2v.z+xb[11]*z2v.w
            +xb[12]*z3.x+xb[13]*z3.y+xb[14]*z3.z+xb[15]*z3.w;
        acca+=za.y*exp2f(ara);
        accb+=za.y*exp2f(arb);
    }
    g_f[p0*16+d]=acca;
    g_f[(p0+1)*16+d]=accb;
}

// ---------- kFlow: RealNVP, 16 points/block, 400 blocks (R11 proven) ----------
struct FLsm {
    float W1[512], b1[32], W2[2048], b2[64], W3[1024], b3[16];
    float cur[16*17];
    float ss[16*9];
    float h1[16*33];
    float h2[16*65];
};

__device__ __forceinline__ void cpy4(float* d, const float* s, int n4, int tid){
    float4* d4=(float4*)d; const float4* s4=(const float4*)s;
    for(int i=tid;i<n4;i+=256) d4[i]=s4[i];
}

__device__ __forceinline__ void stageW(FLsm& sm, const float* W1,const float* b1,
    const float* W2,const float* b2,const float* W3,const float* b3,int l,int tid)
{
    cpy4(sm.W1,W1+l*512,128,tid);  cpy4(sm.b1,b1+l*32,8,tid);
    cpy4(sm.W2,W2+l*2048,512,tid); cpy4(sm.b2,b2+l*64,16,tid);
    cpy4(sm.W3,W3+l*1024,256,tid); cpy4(sm.b3,b3+l*16,4,tid);
}

__device__ __forceinline__ void mlp12(FLsm& sm, int act, int tid){
    for(int idx=tid; idx<512; idx+=256){
        int p=idx&15, j=idx>>4;
        float a=sm.b1[j];
#pragma unroll
        for(int k=0;k<8;++k) a+=sm.cur[p*17+act+k]*sm.W1[j*16+act+k];
        sm.h1[p*33+j]=lrelu(a);
    }
    __syncthreads();
    for(int idx=tid; idx<1024; idx+=256){
        int p=idx&15, j=idx>>4;
        float a=sm.b2[j];
#pragma unroll
        for(int k=0;k<32;++k) a+=sm.h1[p*33+k]*sm.W2[j*32+k];
        sm.h2[p*65+j]=lrelu(a);
    }
    __syncthreads();
}

__global__ void __launch_bounds__(256) kFlow(
    const float* __restrict__ sW1, const float* __restrict__ sb1,
    const float* __restrict__ sW2, const float* __restrict__ sb2,
    const float* __restrict__ sW3, const float* __restrict__ sb3,
    const float* __restrict__ tW1, const float* __restrict__ tb1,
    const float* __restrict__ tW2, const float* __restrict__ tb2,
    const float* __restrict__ tW3, const float* __restrict__ tb3)
{
    __shared__ FLsm sm;
    int tid=threadIdx.x, q0=blockIdx.x*16;
    sm.cur[(tid>>4)*17+(tid&15)]=g_f[q0*16+tid];
    for(int l=0;l<4;++l){
        bool odd=(l&1)!=0;
        int act   = odd?0:8;
        int inact = odd?8:0;
        stageW(sm,sW1,sb1,sW2,sb2,sW3,sb3,l,tid);
        __syncthreads();
        mlp12(sm,act,tid);
        if(tid<128){
            int p=tid&15, j=tid>>4, jd=inact+j;
            float a=sm.b3[jd];
#pragma unroll
            for(int k=0;k<64;++k) a+=sm.h2[p*65+k]*sm.W3[jd*64+k];
            sm.ss[p*9+j]=a;
        }
        __syncthreads();
        stageW(sm,tW1,tb1,tW2,tb2,tW3,tb3,l,tid);
        __syncthreads();
        mlp12(sm,act,tid);
        if(tid<128){
            int p=tid&15, j=tid>>4, jd=inact+j;
            float a=sm.b3[jd];
#pragma unroll
            for(int k=0;k<64;++k) a+=sm.h2[p*65+k]*sm.W3[jd*64+k];
            float xv=sm.cur[p*17+jd];
            sm.cur[p*17+jd]=xv*expf(sm.ss[p*9+j])+a;
        }
        __syncthreads();
    }
    g_state[q0*16+tid]=sm.cur[(tid>>4)*17+(tid&15)];
}

// ---------- kB: EnKF, 512 threads (R11 proven) ----------
__global__ void __launch_bounds__(512) kB_enkf(
    const float* __restrict__ obs, const float* __restrict__ Hg,
    float* __restrict__ out, int t)
{
    __shared__ float Xs[NMC*17], inn[NMC*17];
    __shared__ float Hs[256], Pm[256], Ss[256], Kt[256], PHt[256], KH[256];
    __shared__ float Xm[16], ys[16], dd[16], sol16[16];
    __shared__ float cov2[512], xm4[64];
    int tid=threadIdx.x, b=blockIdx.x;
    for(int i=tid;i<NMC*16;i+=512) Xs[(i>>4)*17+(i&15)]=g_state[b*NMC*16+i];
    if(tid<256) Hs[tid]=Hg[tid];
    if(tid<16) ys[tid]=obs[(b*TT+t)*16+tid];
    __syncthreads();
    if(tid<64){
        int d=tid&15, q=tid>>4;
        float s=0.f;
        for(int n=q*25;n<q*25+25;++n) s+=Xs[n*17+d];
        xm4[tid]=s;
    }
    __syncthreads();
    if(tid<16) Xm[tid]=(xm4[tid]+xm4[16+tid]+xm4[32+tid]+xm4[48+tid])/NMC;
    __syncthreads();
    {
        int pair=tid&255, half=tid>>8;
        int d=pair>>4, e=pair&15;
        float md=Xm[d], me=Xm[e], s=0.f;
        int n0=half*50;
        for(int n=n0;n<n0+50;++n) s+=(Xs[n*17+d]-md)*(Xs[n*17+e]-me);
        cov2[tid]=s;
    }
    __syncthreads();
    if(tid<256){
        int d=tid>>4, e=tid&15;
        Pm[tid]=g_taper[tid]*((cov2[tid]+cov2[tid+256])/(NMC-1))+(d==e?PVAR:0.f);
    }
    __syncthreads();
    if(tid<256){
        int o=tid>>4, d=tid&15;
        float s=0.f;
#pragma unroll
        for(int e=0;e<16;++e) s+=Hs[o*16+e]*Pm[e*16+d];
        PHt[tid]=s;
    }
    __syncthreads();
    if(tid<256){
        int o=tid>>4, pq=tid&15;
        float s=0.f;
#pragma unroll
        for(int d=0;d<16;++d) s+=PHt[o*16+d]*Hs[pq*16+d];
        Ss[tid]=s+(o==pq?EVAR:0.f);
    }
    if(tid>=256&&tid<272){
        int o=tid-256;
        float s=ys[o];
#pragma unroll
        for(int d=0;d<16;++d) s-=Xm[d]*Hs[o*16+d];
        dd[o]=s;
    }
    __syncthreads();
    if(tid<32){
#pragma unroll
        for(int k=0;k<16;++k){
            if(tid==0) Ss[k*16+k]=sqrtf(Ss[k*16+k]);
            __syncwarp();
            if(tid>k&&tid<16) Ss[tid*16+k]/=Ss[k*16+k];
            __syncwarp();
            if(tid>k&&tid<16){
                float lik=Ss[tid*16+k];
                for(int j=k+1;j<=tid;++j) Ss[tid*16+j]-=lik*Ss[j*16+k];
            }
            __syncwarp();
        }
    }
    __syncthreads();
    if(tid<17){
        float w[16], r[16];
#pragma unroll
        for(int i=0;i<16;++i) r[i]= (tid<16)? PHt[i*16+tid] : dd[i];
#pragma unroll
        for(int i=0;i<16;++i){
            float s=r[i];
#pragma unroll
            for(int j=0;j<16;++j) if(j<i) s-=Ss[i*16+j]*w[j];
            w[i]=s/Ss[i*16+i];
        }
#pragma unroll
        for(int i=15;i>=0;--i){
            float s=w[i];
#pragma unroll
            for(int j=15;j>=0;--j) if(j>i) s-=Ss[j*16+i]*w[j];
            w[i]=s/Ss[i*16+i];
        }
        if(tid<16){
#pragma unroll
            for(int i=0;i<16;++i) Kt[i*16+tid]=w[i];
        } else {
#pragma unroll
            for(int i=0;i<16;++i) sol16[i]=w[i];
        }
    }
    __syncthreads();
    for(int idx=tid;idx<NMC*16;idx+=512){
        int n=idx>>4, o=idx&15;
        float s=ys[o];
#pragma unroll
        for(int d=0;d<16;++d) s-=Xs[n*17+d]*Hs[o*16+d];
        inn[n*17+o]=s;
    }
    __syncthreads();
    for(int idx=tid;idx<NMC*16;idx+=512){
        int n=idx>>4, d=idx&15;
        float s=Xs[n*17+d];
#pragma unroll
        for(int o=0;o<16;++o) s+=inn[n*17+o]*Kt[o*16+d];
        Xs[n*17+d]=s;
        g_state[b*NMC*16+idx]=s;
    }
    if(tid<256){
        int d=tid>>4, e=tid&15;
        float s=0.f;
#pragma unroll
        for(int o=0;o<16;++o) s+=Kt[o*16+d]*Hs[o*16+e];
        KH[tid]=s;
    }
    __syncthreads();
    if(tid<64){
        int d=tid&15, q=tid>>4;
        float s=0.f;
        for(int n=q*25;n<q*25+25;++n) s+=Xs[n*17+d];
        xm4[tid]=s;
    }
    __syncthreads();
    if(tid<16){
        out[1+(b*TT+t)*16+tid]=(xm4[tid]+xm4[16+tid]+xm4[32+tid]+xm4[48+tid])/NMC;
        float pv=Pm[tid*16+tid];
#pragma unroll
        for(int e=0;e<16;++e) pv-=KH[tid*16+e]*Pm[e*16+tid];
        out[1+BB*TT*16+(b*TT+t)*16+tid]=pv;
    }
    if(tid==32){
        float quad=0.f, ld=0.f;
#pragma unroll
        for(int o=0;o<16;++o){ quad+=dd[o]*sol16[o]; ld+=logf(Ss[o*16+o]); }
        atomicAdd(&g_ll,(double)(-0.5f*(quad+2.f*ld+16.f*LOG2PI)));
    }
}

__global__ void kF_final(float* out){
    out[0]=(float)(-g_kl0-g_gpkl+g_ll/50.0);
}

extern "C" void kernel_launch(void* const* d_in, const int* in_sizes, int n_in,
                              void* d_out, int out_size)
{
    const float* obs =(const float*)d_in[0];
    const float* eps =(const float*)d_in[1];
    const float* Wih =(const float*)d_in[2];
    const float* Whh =(const float*)d_in[3];
    const float* bl  =(const float*)d_in[4];
    const float* Wm  =(const float*)d_in[5];
    const float* bm  =(const float*)d_in[6];
    const float* Wv  =(const float*)d_in[7];
    const float* bv  =(const float*)d_in[8];
    const float* Z   =(const float*)d_in[9];
    const float* lls =(const float*)d_in[10];
    const float* los =(const float*)d_in[11];
    const float* qmu =(const float*)d_in[12];
    const float* qL  =(const float*)d_in[13];
    const float* sW1 =(const float*)d_in[14];
    const float* sb1 =(const float*)d_in[15];
    const float* sW2 =(const float*)d_in[16];
    const float* sb2 =(const float*)d_in[17];
    const float* sW3 =(const float*)d_in[18];
    const float* sb3 =(const float*)d_in[19];
    const float* tW1 =(const float*)d_in[20];
    const float* tb1 =(const float*)d_in[21];
    const float* tW2 =(const float*)d_in[22];
    const float* tb2 =(const float*)d_in[23];
    const float* tW3 =(const float*)d_in[24];
    const float* tb3 =(const float*)d_in[25];
    const float* Hg  =(const float*)d_in[26];
    float* out=(float*)d_out;

    static int attr_done=0;
    if(!attr_done){
        cudaFuncSetAttribute(k3_gp, cudaFuncAttributeMaxDynamicSharedMemorySize, 80*1024);
        attr_done=1;
    }
    k0_init<<<1,256>>>();
    k1_lstm<<<64,256>>>(obs,eps,Wih,Whh,bl,Wm,bm,Wv,bv);
    k3_gp<<<16,128,80*1024>>>(Z,lls,los,qmu,qL);
    dim3 gGP(16,25);
    for(int t=0;t<TT;++t){
        kGP<<<gGP,128>>>(Z);
        kFlow<<<400,256>>>(sW1,sb1,sW2,sb2,sW3,sb3,tW1,tb1,tW2,tb2,tW3,tb3);
        kB_enkf<<<64,512>>>(obs,Hg,out,t);
    }
    kF_final<<<1,1>>>(out);
}